// round 2
// baseline (speedup 1.0000x reference)
#include <cuda_runtime.h>

// Problem constants
#define T_LEN 1024
#define D_IN  1024
#define H_HID 512
#define G4    2048      // 4*H
#define BATCH 32
#define KTOT  1536      // D + H
#define KT    64        // k-tile
#define NT    24        // KTOT / KT  (tiles 0..15 = x part, 16..23 = h part)
#define NBLK  128       // 2 dirs * 64 blocks (8 hidden units each)
#define NTHR  128

// ---------------- device scratch (no allocations allowed) ----------------
__device__ float g_xT[(size_t)T_LEN * D_IN * BATCH];   // [t][k][b]  128 MB
__device__ float g_hbuf[2][2][H_HID * BATCH];          // [buf][dir][j*32+b]
__device__ float g_part[NBLK][T_LEN][BATCH];           // per-block logit partials
__device__ unsigned int          g_bar_count;
__device__ volatile unsigned int g_bar_gen;

// ---------------- f32x2 packed math ----------------
__device__ __forceinline__ unsigned long long splat2(float v) {
    unsigned long long r; unsigned u = __float_as_uint(v);
    asm("mov.b64 %0, {%1, %1};" : "=l"(r) : "r"(u));
    return r;
}
#define FMA2(acc, xv, wv) \
    asm("fma.rn.f32x2 %0, %1, %2, %0;" : "+l"(acc) : "l"(xv), "l"(wv))

__device__ __forceinline__ void unpack2(unsigned long long a, float& lo, float& hi) {
    unsigned l, h;
    asm("mov.b64 {%0, %1}, %2;" : "=r"(l), "=r"(h) : "l"(a));
    lo = __uint_as_float(l); hi = __uint_as_float(h);
}

// ---------------- grid barrier (all 128 blocks resident) ----------------
__device__ __forceinline__ void grid_sync_dev(unsigned nblocks) {
    __syncthreads();
    if (threadIdx.x == 0) {
        __threadfence();
        unsigned gen = g_bar_gen;
        if (atomicAdd(&g_bar_count, 1u) == nblocks - 1u) {
            g_bar_count = 0;
            __threadfence();
            g_bar_gen = gen + 1u;
        } else {
            while (g_bar_gen == gen) { }
        }
        __threadfence();
    }
    __syncthreads();
}

// ---------------- kernel 1: zero recurrent state ----------------
__global__ void zero_state_kernel() {
    int i = blockIdx.x * blockDim.x + threadIdx.x;
    if (i < 2 * 2 * H_HID * BATCH) ((float*)g_hbuf)[i] = 0.0f;
}

// ---------------- kernel 2: transpose x[B][T][D] -> xT[t][k][b] ----------------
__global__ void transpose_x_kernel(const float* __restrict__ x) {
    __shared__ float tile[32][33];
    int t  = blockIdx.x;
    int k0 = blockIdx.y * 32;
    int tid = threadIdx.x;              // 256 threads
    int kk = tid & 31, r = tid >> 5;    // r in 0..7
#pragma unroll
    for (int i = 0; i < 4; ++i) {
        int b = r + i * 8;
        tile[kk][b] = x[((size_t)b * T_LEN + t) * D_IN + k0 + kk];
    }
    __syncthreads();
    int b2 = tid & 31, kr = tid >> 5;
#pragma unroll
    for (int i = 0; i < 4; ++i) {
        int kk2 = kr + i * 8;
        g_xT[((size_t)t * D_IN + k0 + kk2) * BATCH + b2] = tile[kk2][b2];
    }
}

// ---------------- tile staging helpers ----------------
__device__ __forceinline__ void load_tile_regs(
    int ti, int t, const float* __restrict__ hprev,
    const float* __restrict__ Wx, const float* __restrict__ Wh,
    int j0, int tid, float4* xr, float4* wr)
{
    int k0 = ti * KT;
    const float* xsrc = (k0 < D_IN)
        ? (g_xT + ((size_t)t * D_IN + k0) * BATCH)
        : (hprev + (size_t)(k0 - D_IN) * BATCH);
    const float4* xp = reinterpret_cast<const float4*>(xsrc);
    const float* wbase = (k0 < D_IN)
        ? (Wx + (size_t)k0 * G4)
        : (Wh + (size_t)(k0 - D_IN) * G4);
#pragma unroll
    for (int i = 0; i < 4; ++i) {
        int q = tid + i * 128;
        xr[i] = xp[q];
        int kk = q >> 3, rem = q & 7;
        wr[i] = *reinterpret_cast<const float4*>(
            wbase + (size_t)kk * G4 + (rem >> 1) * H_HID + j0 + (rem & 1) * 4);
    }
}

__device__ __forceinline__ void store_tile_smem(
    float4* __restrict__ xsb, float4* __restrict__ wsb,
    int tid, const float4* xr, const float4* wr)
{
#pragma unroll
    for (int i = 0; i < 4; ++i) {
        int q = tid + i * 128;
        xsb[q] = xr[i];
        wsb[q] = wr[i];
    }
}

// ---------------- kernel 3: persistent bidirectional LSTM ----------------
__global__ void __launch_bounds__(NTHR, 1)
lstm_persistent_kernel(const float* __restrict__ Wx_f, const float* __restrict__ Wh_f,
                       const float* __restrict__ b_f,
                       const float* __restrict__ Wx_b, const float* __restrict__ Wh_b,
                       const float* __restrict__ b_b,
                       const float* __restrict__ Wfc)
{
    __shared__ __align__(16) float xs[2][KT * BATCH];  // input tiles  [kk][b]
    __shared__ __align__(16) float ws[2][KT * 32];     // weight tiles [kk][cc]
    __shared__ float gsh[32 * BATCH];                  // gates [cc][b]
    __shared__ float cst[8 * BATCH];                   // cell state [jj][b]
    __shared__ float psum[NTHR];

    const int tid  = threadIdx.x;
    const int w    = tid >> 5;        // warp id: b-group
    const int lane = tid & 31;        // column within block's 32 gate cols
    const int blk  = blockIdx.x;
    const int dir  = blk >> 6;        // 0 = fwd, 1 = bwd
    const int j0   = (blk & 63) * 8;  // hidden-unit base
    const int gate = lane >> 3, u = lane & 7;
    const int c    = gate * H_HID + j0 + u;   // global gate column

    const float* Wx   = dir ? Wx_b : Wx_f;
    const float* Wh   = dir ? Wh_b : Wh_f;
    const float* bias = dir ? b_b  : b_f;

    const unsigned long long bias2 = splat2(bias[c]);

    // cell-state init (slots tid and tid+128 are thread-private)
    cst[tid] = 0.0f;
    if (tid + 128 < 8 * BATCH) cst[tid + 128] = 0.0f;

    // FC weights for this thread's elementwise items
    const int jjA = tid >> 5;          // item0: jj = jjA, item1: jj = jjA+4
    const float wfcA = Wfc[dir * H_HID + j0 + jjA];
    const float wfcB = Wfc[dir * H_HID + j0 + jjA + 4];

    for (int s = 0; s < T_LEN; ++s) {
        const int t = dir ? (T_LEN - 1 - s) : s;
        const float* hprev = g_hbuf[s & 1][dir];
        float*       hnext = g_hbuf[(s + 1) & 1][dir];

        unsigned long long a0 = bias2, a1 = bias2, a2 = bias2, a3 = bias2;

        // prologue: stage tile 0
        {
            float4 xr[4], wr[4];
            load_tile_regs(0, t, hprev, Wx, Wh, j0, tid, xr, wr);
            store_tile_smem((float4*)xs[0], (float4*)ws[0], tid, xr, wr);
        }
        __syncthreads();

        for (int ti = 0; ti < NT; ++ti) {
            float4 xr[4], wr[4];
            if (ti + 1 < NT)
                load_tile_regs(ti + 1, t, hprev, Wx, Wh, j0, tid, xr, wr);

            const float* xb = xs[ti & 1] + 8 * w;
            const float* wb = ws[ti & 1] + lane;
#pragma unroll 8
            for (int kk = 0; kk < KT; ++kk) {
                ulonglong2 p0 = *reinterpret_cast<const ulonglong2*>(xb);
                ulonglong2 p1 = *reinterpret_cast<const ulonglong2*>(xb + 4);
                unsigned long long w2 = splat2(*wb);
                FMA2(a0, p0.x, w2);
                FMA2(a1, p0.y, w2);
                FMA2(a2, p1.x, w2);
                FMA2(a3, p1.y, w2);
                xb += BATCH; wb += 32;
            }

            if (ti + 1 < NT)
                store_tile_smem((float4*)xs[(ti + 1) & 1], (float4*)ws[(ti + 1) & 1],
                                tid, xr, wr);
            __syncthreads();
        }

        // write gate pre-activations to smem: gsh[cc][b]
        {
            float v0, v1;
            float* gp = gsh + lane * BATCH + 8 * w;
            unpack2(a0, v0, v1); gp[0] = v0; gp[1] = v1;
            unpack2(a1, v0, v1); gp[2] = v0; gp[3] = v1;
            unpack2(a2, v0, v1); gp[4] = v0; gp[5] = v1;
            unpack2(a3, v0, v1); gp[6] = v0; gp[7] = v1;
        }
        __syncthreads();

        // elementwise LSTM cell: items tid (jj=tid>>5) and tid+128 (jj+4), b=tid&31
        float part = 0.0f;
#pragma unroll
        for (int it = 0; it < 2; ++it) {
            int item = tid + it * 128;
            int jj = item >> 5;
            int b  = item & 31;
            float iv = gsh[(0 * 8 + jj) * BATCH + b];
            float fv = gsh[(1 * 8 + jj) * BATCH + b];
            float gv = gsh[(2 * 8 + jj) * BATCH + b];
            float ov = gsh[(3 * 8 + jj) * BATCH + b];
            iv = 1.0f / (1.0f + __expf(-iv));
            fv = 1.0f / (1.0f + __expf(-fv));
            gv = tanhf(gv);
            ov = 1.0f / (1.0f + __expf(-ov));
            float cv = fv * cst[item] + iv * gv;
            cst[item] = cv;
            float hv = ov * tanhf(cv);
            hnext[(j0 + jj) * BATCH + b] = hv;
            part += hv * (it == 0 ? wfcA : wfcB);
        }
        psum[tid] = part;
        __syncthreads();
        if (tid < BATCH) {
            float tot = psum[tid] + psum[tid + 32] + psum[tid + 64] + psum[tid + 96];
            g_part[blk][t][tid] = tot;
        }

        if (s != T_LEN - 1) grid_sync_dev(gridDim.x);
    }
}

// ---------------- kernel 4: reduce partials + sigmoid ----------------
__global__ void finalize_kernel(const float* __restrict__ b_fc, float* __restrict__ out) {
    int g = blockIdx.x * blockDim.x + threadIdx.x;   // 32768
    if (g >= T_LEN * BATCH) return;
    int t = g >> 5, b = g & 31;
    float acc = b_fc[0];
    const float* p = &g_part[0][t][b];
#pragma unroll 8
    for (int blk = 0; blk < NBLK; ++blk)
        acc += p[(size_t)blk * T_LEN * BATCH];
    out[(size_t)b * T_LEN + t] = 1.0f / (1.0f + __expf(-acc));
}

// ---------------- launcher ----------------
extern "C" void kernel_launch(void* const* d_in, const int* in_sizes, int n_in,
                              void* d_out, int out_size) {
    const float* x    = (const float*)d_in[0];
    const float* Wx_f = (const float*)d_in[1];
    const float* Wh_f = (const float*)d_in[2];
    const float* b_f  = (const float*)d_in[3];
    const float* Wx_b = (const float*)d_in[4];
    const float* Wh_b = (const float*)d_in[5];
    const float* b_b  = (const float*)d_in[6];
    const float* Wfc  = (const float*)d_in[7];
    const float* bfc  = (const float*)d_in[8];
    float* out = (float*)d_out;
    (void)in_sizes; (void)n_in; (void)out_size;

    zero_state_kernel<<<256, 256>>>();
    transpose_x_kernel<<<dim3(T_LEN, D_IN / 32), 256>>>(x);
    lstm_persistent_kernel<<<NBLK, NTHR>>>(Wx_f, Wh_f, b_f, Wx_b, Wh_b, b_b, Wfc);
    finalize_kernel<<<(T_LEN * BATCH + 255) / 256, 256>>>(bfc, out);
}

// round 3
// speedup vs baseline: 1.0028x; 1.0028x over previous
#include <cuda_runtime.h>

// Problem constants
#define T_LEN 1024
#define D_IN  1024
#define H_HID 512
#define G4    2048      // 4*H
#define BATCH 32
#define KTOT  1536      // D + H
#define KT    64        // k-tile
#define NT    24        // KTOT / KT  (tiles 0..15 = x part, 16..23 = h part)
#define NBLK  128       // 2 dirs * 64 blocks (8 hidden units each)
#define NTHR  128

// ---------------- device scratch (no allocations allowed) ----------------
__device__ float g_xT[(size_t)T_LEN * D_IN * BATCH];   // [t][k][b]  128 MB
__device__ float g_hbuf[2][2][H_HID * BATCH];          // [buf][dir][j*32+b]
__device__ float g_part[NBLK][T_LEN][BATCH];           // per-block logit partials
__device__ unsigned int          g_bar_count;
__device__ volatile unsigned int g_bar_gen;

// ---------------- f32x2 packed math ----------------
__device__ __forceinline__ unsigned long long splat2(float v) {
    unsigned long long r; unsigned u = __float_as_uint(v);
    asm("mov.b64 %0, {%1, %1};" : "=l"(r) : "r"(u));
    return r;
}
#define FMA2(acc, xv, wv) \
    asm("fma.rn.f32x2 %0, %1, %2, %0;" : "+l"(acc) : "l"(xv), "l"(wv))

__device__ __forceinline__ void unpack2(unsigned long long a, float& lo, float& hi) {
    unsigned l, h;
    asm("mov.b64 {%0, %1}, %2;" : "=r"(l), "=r"(h) : "l"(a));
    lo = __uint_as_float(l); hi = __uint_as_float(h);
}

// ---------------- grid barrier (all 128 blocks resident) ----------------
__device__ __forceinline__ void grid_sync_dev(unsigned nblocks) {
    __syncthreads();
    if (threadIdx.x == 0) {
        __threadfence();
        unsigned gen = g_bar_gen;
        if (atomicAdd(&g_bar_count, 1u) == nblocks - 1u) {
            g_bar_count = 0;
            __threadfence();
            g_bar_gen = gen + 1u;
        } else {
            while (g_bar_gen == gen) { }
        }
        __threadfence();
    }
    __syncthreads();
}

// ---------------- kernel 1: zero recurrent state ----------------
__global__ void zero_state_kernel() {
    int i = blockIdx.x * blockDim.x + threadIdx.x;
    if (i < 2 * 2 * H_HID * BATCH) ((float*)g_hbuf)[i] = 0.0f;
}

// ---------------- kernel 2: transpose x[B][T][D] -> xT[t][k][b] ----------------
__global__ void transpose_x_kernel(const float* __restrict__ x) {
    __shared__ float tile[32][33];
    int t  = blockIdx.x;
    int k0 = blockIdx.y * 32;
    int tid = threadIdx.x;              // 256 threads
    int kk = tid & 31, r = tid >> 5;    // r in 0..7
#pragma unroll
    for (int i = 0; i < 4; ++i) {
        int b = r + i * 8;
        tile[kk][b] = x[((size_t)b * T_LEN + t) * D_IN + k0 + kk];
    }
    __syncthreads();
    int b2 = tid & 31, kr = tid >> 5;
#pragma unroll
    for (int i = 0; i < 4; ++i) {
        int kk2 = kr + i * 8;
        g_xT[((size_t)t * D_IN + k0 + kk2) * BATCH + b2] = tile[kk2][b2];
    }
}

// ---------------- tile staging helpers ----------------
__device__ __forceinline__ void load_tile_regs(
    int ti, int t, const float* __restrict__ hprev,
    const float* __restrict__ Wx, const float* __restrict__ Wh,
    int j0, int tid, float4* xr, float4* wr)
{
    int k0 = ti * KT;
    const float* xsrc = (k0 < D_IN)
        ? (g_xT + ((size_t)t * D_IN + k0) * BATCH)
        : (hprev + (size_t)(k0 - D_IN) * BATCH);
    const float4* xp = reinterpret_cast<const float4*>(xsrc);
    const float* wbase = (k0 < D_IN)
        ? (Wx + (size_t)k0 * G4)
        : (Wh + (size_t)(k0 - D_IN) * G4);
#pragma unroll
    for (int i = 0; i < 4; ++i) {
        int q = tid + i * 128;
        xr[i] = xp[q];
        int kk = q >> 3, rem = q & 7;
        wr[i] = *reinterpret_cast<const float4*>(
            wbase + (size_t)kk * G4 + (rem >> 1) * H_HID + j0 + (rem & 1) * 4);
    }
}

__device__ __forceinline__ void store_tile_smem(
    float4* __restrict__ xsb, float4* __restrict__ wsb,
    int tid, const float4* xr, const float4* wr)
{
#pragma unroll
    for (int i = 0; i < 4; ++i) {
        int q = tid + i * 128;
        xsb[q] = xr[i];
        wsb[q] = wr[i];
    }
}

// ---------------- kernel 3: persistent bidirectional LSTM ----------------
__global__ void __launch_bounds__(NTHR, 1)
lstm_persistent_kernel(const float* __restrict__ Wx_f, const float* __restrict__ Wh_f,
                       const float* __restrict__ b_f,
                       const float* __restrict__ Wx_b, const float* __restrict__ Wh_b,
                       const float* __restrict__ b_b,
                       const float* __restrict__ Wfc)
{
    __shared__ __align__(16) float xs[2][KT * BATCH];  // input tiles  [kk][b]
    __shared__ __align__(16) float ws[2][KT * 32];     // weight tiles [kk][cc]
    __shared__ float gsh[32 * BATCH];                  // gates [cc][b]
    __shared__ float cst[8 * BATCH];                   // cell state [jj][b]
    __shared__ float psum[NTHR];

    const int tid  = threadIdx.x;
    const int w    = tid >> 5;        // warp id: b-group
    const int lane = tid & 31;        // column within block's 32 gate cols
    const int blk  = blockIdx.x;
    const int dir  = blk >> 6;        // 0 = fwd, 1 = bwd
    const int j0   = (blk & 63) * 8;  // hidden-unit base
    const int gate = lane >> 3, u = lane & 7;
    const int c    = gate * H_HID + j0 + u;   // global gate column

    const float* Wx   = dir ? Wx_b : Wx_f;
    const float* Wh   = dir ? Wh_b : Wh_f;
    const float* bias = dir ? b_b  : b_f;

    const unsigned long long bias2 = splat2(bias[c]);

    // cell-state init (slots tid and tid+128 are thread-private)
    cst[tid] = 0.0f;
    if (tid + 128 < 8 * BATCH) cst[tid + 128] = 0.0f;

    // FC weights for this thread's elementwise items
    const int jjA = tid >> 5;          // item0: jj = jjA, item1: jj = jjA+4
    const float wfcA = Wfc[dir * H_HID + j0 + jjA];
    const float wfcB = Wfc[dir * H_HID + j0 + jjA + 4];

    for (int s = 0; s < T_LEN; ++s) {
        const int t = dir ? (T_LEN - 1 - s) : s;
        const float* hprev = g_hbuf[s & 1][dir];
        float*       hnext = g_hbuf[(s + 1) & 1][dir];

        unsigned long long a0 = bias2, a1 = bias2, a2 = bias2, a3 = bias2;

        // prologue: stage tile 0
        {
            float4 xr[4], wr[4];
            load_tile_regs(0, t, hprev, Wx, Wh, j0, tid, xr, wr);
            store_tile_smem((float4*)xs[0], (float4*)ws[0], tid, xr, wr);
        }
        __syncthreads();

        for (int ti = 0; ti < NT; ++ti) {
            float4 xr[4], wr[4];
            if (ti + 1 < NT)
                load_tile_regs(ti + 1, t, hprev, Wx, Wh, j0, tid, xr, wr);

            const float* xb = xs[ti & 1] + 8 * w;
            const float* wb = ws[ti & 1] + lane;
#pragma unroll 8
            for (int kk = 0; kk < KT; ++kk) {
                ulonglong2 p0 = *reinterpret_cast<const ulonglong2*>(xb);
                ulonglong2 p1 = *reinterpret_cast<const ulonglong2*>(xb + 4);
                unsigned long long w2 = splat2(*wb);
                FMA2(a0, p0.x, w2);
                FMA2(a1, p0.y, w2);
                FMA2(a2, p1.x, w2);
                FMA2(a3, p1.y, w2);
                xb += BATCH; wb += 32;
            }

            if (ti + 1 < NT)
                store_tile_smem((float4*)xs[(ti + 1) & 1], (float4*)ws[(ti + 1) & 1],
                                tid, xr, wr);
            __syncthreads();
        }

        // write gate pre-activations to smem: gsh[cc][b]
        {
            float v0, v1;
            float* gp = gsh + lane * BATCH + 8 * w;
            unpack2(a0, v0, v1); gp[0] = v0; gp[1] = v1;
            unpack2(a1, v0, v1); gp[2] = v0; gp[3] = v1;
            unpack2(a2, v0, v1); gp[4] = v0; gp[5] = v1;
            unpack2(a3, v0, v1); gp[6] = v0; gp[7] = v1;
        }
        __syncthreads();

        // elementwise LSTM cell: items tid (jj=tid>>5) and tid+128 (jj+4), b=tid&31
        float part = 0.0f;
#pragma unroll
        for (int it = 0; it < 2; ++it) {
            int item = tid + it * 128;
            int jj = item >> 5;
            int b  = item & 31;
            float iv = gsh[(0 * 8 + jj) * BATCH + b];
            float fv = gsh[(1 * 8 + jj) * BATCH + b];
            float gv = gsh[(2 * 8 + jj) * BATCH + b];
            float ov = gsh[(3 * 8 + jj) * BATCH + b];
            iv = 1.0f / (1.0f + __expf(-iv));
            fv = 1.0f / (1.0f + __expf(-fv));
            gv = tanhf(gv);
            ov = 1.0f / (1.0f + __expf(-ov));
            float cv = fv * cst[item] + iv * gv;
            cst[item] = cv;
            float hv = ov * tanhf(cv);
            hnext[(j0 + jj) * BATCH + b] = hv;
            part += hv * (it == 0 ? wfcA : wfcB);
        }
        psum[tid] = part;
        __syncthreads();
        if (tid < BATCH) {
            float tot = psum[tid] + psum[tid + 32] + psum[tid + 64] + psum[tid + 96];
            g_part[blk][t][tid] = tot;
        }

        if (s != T_LEN - 1) grid_sync_dev(gridDim.x);
    }
}

// ---------------- kernel 4: reduce partials + sigmoid ----------------
__global__ void finalize_kernel(const float* __restrict__ b_fc, float* __restrict__ out) {
    int g = blockIdx.x * blockDim.x + threadIdx.x;   // 32768
    if (g >= T_LEN * BATCH) return;
    int t = g >> 5, b = g & 31;
    float acc = b_fc[0];
    const float* p = &g_part[0][t][b];
#pragma unroll 8
    for (int blk = 0; blk < NBLK; ++blk)
        acc += p[(size_t)blk * T_LEN * BATCH];
    out[(size_t)b * T_LEN + t] = 1.0f / (1.0f + __expf(-acc));
}

// ---------------- launcher ----------------
extern "C" void kernel_launch(void* const* d_in, const int* in_sizes, int n_in,
                              void* d_out, int out_size) {
    const float* x    = (const float*)d_in[0];
    const float* Wx_f = (const float*)d_in[1];
    const float* Wh_f = (const float*)d_in[2];
    const float* b_f  = (const float*)d_in[3];
    const float* Wx_b = (const float*)d_in[4];
    const float* Wh_b = (const float*)d_in[5];
    const float* b_b  = (const float*)d_in[6];
    const float* Wfc  = (const float*)d_in[7];
    const float* bfc  = (const float*)d_in[8];
    float* out = (float*)d_out;
    (void)in_sizes; (void)n_in; (void)out_size;

    zero_state_kernel<<<256, 256>>>();
    transpose_x_kernel<<<dim3(T_LEN, D_IN / 32), 256>>>(x);
    lstm_persistent_kernel<<<NBLK, NTHR>>>(Wx_f, Wh_f, b_f, Wx_b, Wh_b, b_b, Wfc);
    finalize_kernel<<<(T_LEN * BATCH + 255) / 256, 256>>>(bfc, out);
}

// round 4
// speedup vs baseline: 1.6481x; 1.6435x over previous
#include <cuda_runtime.h>

#define T_LEN 1024
#define D_IN  1024
#define H_HID 512
#define G4    2048
#define BATCH 32
#define ROWS  32768          // T*B
#define NCOL  4096           // 2 dirs * 4H

// ---------------- device scratch ----------------
__device__ float g_xA[(size_t)D_IN * ROWS];     // x transposed: [k][row], row = t*32+b
__device__ float g_xg[(size_t)NCOL * ROWS];     // input projections, col-major: [col][row]
__device__ float g_hbuf[2][2][H_HID * BATCH];   // [buf][dir][j*32+b]
__device__ float g_part[128][T_LEN][BATCH];     // per-block logit partials
__device__ unsigned g_cnt[2];
__device__ unsigned g_gen[2];

// ---------------- f32x2 helpers ----------------
__device__ __forceinline__ unsigned long long splat2(float v) {
    unsigned long long r; unsigned u = __float_as_uint(v);
    asm("mov.b64 %0, {%1, %1};" : "=l"(r) : "r"(u));
    return r;
}
#define FMA2(acc, xv, wv) \
    asm("fma.rn.f32x2 %0, %1, %2, %0;" : "+l"(acc) : "l"(xv), "l"(wv))
__device__ __forceinline__ void unpack2(unsigned long long a, float& lo, float& hi) {
    unsigned l, h;
    asm("mov.b64 {%0, %1}, %2;" : "=r"(l), "=r"(h) : "l"(a));
    lo = __uint_as_float(l); hi = __uint_as_float(h);
}

// ---------------- per-direction grid barrier ----------------
__device__ __forceinline__ void bar_sync(int idx, unsigned count) {
    __syncthreads();
    if (threadIdx.x == 0) {
        __threadfence();
        unsigned gen = ((volatile unsigned*)g_gen)[idx];
        if (atomicAdd(&g_cnt[idx], 1u) == count - 1u) {
            g_cnt[idx] = 0;
            __threadfence();
            ((volatile unsigned*)g_gen)[idx] = gen + 1u;
        } else {
            while (((volatile unsigned*)g_gen)[idx] == gen) { }
        }
        __threadfence();
    }
    __syncthreads();
}

// ---------------- kernel 1: zero recurrent state ----------------
__global__ void zero_state_kernel() {
    int i = blockIdx.x * blockDim.x + threadIdx.x;
    ((float*)g_hbuf)[i] = 0.0f;       // 65536 threads exactly
}

// ---------------- kernel 2: transpose x[B][T][D] -> xA[k][t*32+b] ----------------
__global__ void transpose_x_kernel(const float* __restrict__ x) {
    __shared__ float tile[32][33];
    int t = blockIdx.x, k0 = blockIdx.y * 32, tid = threadIdx.x;
    int kk = tid & 31, r = tid >> 5;
#pragma unroll
    for (int i = 0; i < 4; ++i) {
        int b = r + i * 8;
        tile[kk][b] = x[((size_t)b * T_LEN + t) * D_IN + k0 + kk];
    }
    __syncthreads();
    int b2 = tid & 31, kr = tid >> 5;
#pragma unroll
    for (int i = 0; i < 4; ++i) {
        int kk2 = kr + i * 8;
        g_xA[(size_t)(k0 + kk2) * ROWS + t * 32 + b2] = tile[kk2][b2];
    }
}

// ---------------- kernel 3: xg = A @ [Wx_f | Wx_b]  (fp32 FFMA2 GEMM) ----------------
// block tile: 128 rows x 64 cols, kt=32, 256 threads, acc = 8 rows x 4 cols per thread
__global__ void __launch_bounds__(256)
gemm_kernel(const float* __restrict__ Wx_f, const float* __restrict__ Wx_b) {
    extern __shared__ float sm[];
    float* xs  = sm;          // [2][32*128]  A tile  [kk][row]
    float* ws2 = sm + 8192;   // [2][32*128]  W tile, duplicated pairs [kk][col*2]

    const int tid = threadIdx.x;
    const int cb = blockIdx.x, rb = blockIdx.y;
    const int r = tid & 15, cg = tid >> 4;    // r: row-octet, cg: col-quad

    unsigned long long acc[4][4];
#pragma unroll
    for (int p = 0; p < 4; ++p)
#pragma unroll
        for (int c = 0; c < 4; ++c) acc[p][c] = 0ull;

    float4 ar[4], wr[2];

    auto load_regs = [&](int ti) {
        int k0 = ti * 32;
#pragma unroll
        for (int i = 0; i < 4; ++i) {
            int f = tid + i * 256;
            int kk = f >> 5, rc = (f & 31) * 4;
            ar[i] = *(const float4*)(g_xA + (size_t)(k0 + kk) * ROWS + rb * 128 + rc);
        }
#pragma unroll
        for (int i = 0; i < 2; ++i) {
            int f = tid + i * 256;
            int kk = f >> 4, cc = (f & 15) * 4;
            int gcol = cb * 64 + cc;
            const float* src = (gcol < G4)
                ? (Wx_f + (size_t)(k0 + kk) * G4 + gcol)
                : (Wx_b + (size_t)(k0 + kk) * G4 + (gcol - G4));
            wr[i] = *(const float4*)src;
        }
    };
    auto store_smem = [&](int buf) {
        float* xb = xs + buf * 4096;
        float* wb = ws2 + buf * 4096;
#pragma unroll
        for (int i = 0; i < 4; ++i) {
            int f = tid + i * 256;
            int kk = f >> 5, rc = (f & 31) * 4;
            *(float4*)(xb + kk * 128 + rc) = ar[i];
        }
#pragma unroll
        for (int i = 0; i < 2; ++i) {
            int f = tid + i * 256;
            int kk = f >> 4, cc = (f & 15) * 4;
            float4 w = wr[i];
            *(float4*)(wb + kk * 128 + cc * 2)     = make_float4(w.x, w.x, w.y, w.y);
            *(float4*)(wb + kk * 128 + cc * 2 + 4) = make_float4(w.z, w.z, w.w, w.w);
        }
    };

    load_regs(0);
    store_smem(0);
    __syncthreads();

    for (int ti = 0; ti < 32; ++ti) {
        if (ti + 1 < 32) load_regs(ti + 1);
        const float* xb = xs + (ti & 1) * 4096 + r * 8;
        const float* wb = ws2 + (ti & 1) * 4096 + cg * 8;
#pragma unroll 4
        for (int kk = 0; kk < 32; ++kk) {
            ulonglong2 xq0 = *(const ulonglong2*)(xb);
            ulonglong2 xq1 = *(const ulonglong2*)(xb + 4);
            ulonglong2 wq0 = *(const ulonglong2*)(wb);
            ulonglong2 wq1 = *(const ulonglong2*)(wb + 4);
            FMA2(acc[0][0], xq0.x, wq0.x); FMA2(acc[0][1], xq0.x, wq0.y);
            FMA2(acc[0][2], xq0.x, wq1.x); FMA2(acc[0][3], xq0.x, wq1.y);
            FMA2(acc[1][0], xq0.y, wq0.x); FMA2(acc[1][1], xq0.y, wq0.y);
            FMA2(acc[1][2], xq0.y, wq1.x); FMA2(acc[1][3], xq0.y, wq1.y);
            FMA2(acc[2][0], xq1.x, wq0.x); FMA2(acc[2][1], xq1.x, wq0.y);
            FMA2(acc[2][2], xq1.x, wq1.x); FMA2(acc[2][3], xq1.x, wq1.y);
            FMA2(acc[3][0], xq1.y, wq0.x); FMA2(acc[3][1], xq1.y, wq0.y);
            FMA2(acc[3][2], xq1.y, wq1.x); FMA2(acc[3][3], xq1.y, wq1.y);
            xb += 128; wb += 128;
        }
        if (ti + 1 < 32) store_smem((ti + 1) & 1);
        __syncthreads();
    }

    // epilogue: col-major store g_xg[col][row]; thread owns rows rb*128+r*8..+7
#pragma unroll
    for (int c = 0; c < 4; ++c) {
        float v[8];
#pragma unroll
        for (int p = 0; p < 4; ++p) unpack2(acc[p][c], v[2 * p], v[2 * p + 1]);
        size_t col = (size_t)cb * 64 + cg * 4 + c;
        float* d = g_xg + col * ROWS + rb * 128 + r * 8;
        *(float4*)d       = make_float4(v[0], v[1], v[2], v[3]);
        *(float4*)(d + 4) = make_float4(v[4], v[5], v[6], v[7]);
    }
}

// ---------------- kernel 4: persistent recurrent phase ----------------
// 128 blocks: dir = blk>>6, block owns 8 hidden units (j0 = (blk&63)*8),
// i.e. 32 gate columns cc = g*8+u. 256 threads, 4-way k-split.
__global__ void __launch_bounds__(256, 1)
lstm_kernel(const float* __restrict__ Wh_f, const float* __restrict__ Wh_b,
            const float* __restrict__ b_f,  const float* __restrict__ b_b,
            const float* __restrict__ Wfc)
{
    extern __shared__ float sm[];
    float* hs   = sm;             // 16384 : h(t-1) [k][b]
    float* ws   = sm + 16384;     // 16384 : Wh slice [kk][cc]
    float* part = sm + 32768;     // 4096  : k-split partials [slice][cc][b]
    float* psum = sm + 36864;     // 256   : logit partial reduction

    const int tid = threadIdx.x;
    const int blk = blockIdx.x;
    const int dir = blk >> 6;
    const int j0  = (blk & 63) * 8;

    // k-loop mapping
    const int slice = tid >> 6;          // 0..3  (k range slice*128..+127)
    const int q     = tid & 63;
    const int cp    = q & 15;            // column pair: cols 2cp, 2cp+1
    const int bo    = q >> 4;            // batch octet: b = bo*8..+7

    // cell mapping
    const int u = tid >> 5;              // hidden unit 0..7
    const int b = tid & 31;              // batch

    const float* Wh   = dir ? Wh_b : Wh_f;
    const float* bias = dir ? b_b  : b_f;

    // load Wh slice into smem once: ws[kk*32 + g*8+u] = Wh[kk][g*512 + j0 + u]
    for (int e = tid; e < 512 * 32; e += 256) {
        int kk = e >> 5, cc = e & 31;
        int g = cc >> 3, uu = cc & 7;
        ws[e] = Wh[(size_t)kk * G4 + g * 512 + j0 + uu];
    }

    float biasr[4], wfc;
#pragma unroll
    for (int g = 0; g < 4; ++g) biasr[g] = bias[g * 512 + j0 + u];
    wfc = Wfc[dir * H_HID + j0 + u];

    float cstate = 0.0f;
    __syncthreads();

    for (int s = 0; s < T_LEN; ++s) {
        const int t = dir ? (T_LEN - 1 - s) : s;
        const float* hprev = g_hbuf[s & 1][dir];
        float*       hnext = g_hbuf[(s + 1) & 1][dir];

        // stage h(t-1): 64KB straight copy
        {
            const float4* src = (const float4*)hprev;
            float4* dst = (float4*)hs;
#pragma unroll
            for (int i = 0; i < 16; ++i) dst[tid + i * 256] = src[tid + i * 256];
        }
        // prefetch this thread's xg values (consumed in epilogue)
        float xgv[4];
#pragma unroll
        for (int g = 0; g < 4; ++g)
            xgv[g] = __ldg(g_xg + (size_t)(dir * G4 + g * 512 + j0 + u) * ROWS + t * 32 + b);
        __syncthreads();

        // k-loop: 128 k's per slice, 8 FMA2 per k
        unsigned long long a0[4], a1[4];
#pragma unroll
        for (int p = 0; p < 4; ++p) { a0[p] = 0ull; a1[p] = 0ull; }
        {
            const float* hp = hs + slice * 128 * 32 + bo * 8;
            const float* wp = ws + slice * 128 * 32 + 2 * cp;
#pragma unroll 4
            for (int kk = 0; kk < 128; ++kk) {
                ulonglong2 hq0 = *(const ulonglong2*)hp;
                ulonglong2 hq1 = *(const ulonglong2*)(hp + 4);
                unsigned long long w0 = splat2(wp[0]);
                unsigned long long w1 = splat2(wp[1]);
                FMA2(a0[0], hq0.x, w0); FMA2(a0[1], hq0.y, w0);
                FMA2(a0[2], hq1.x, w0); FMA2(a0[3], hq1.y, w0);
                FMA2(a1[0], hq0.x, w1); FMA2(a1[1], hq0.y, w1);
                FMA2(a1[2], hq1.x, w1); FMA2(a1[3], hq1.y, w1);
                hp += 32; wp += 32;
            }
        }
        // write k-split partials
        {
            float* p0 = part + slice * 1024 + (2 * cp) * 32 + bo * 8;
            float* p1 = p0 + 32;
            *(ulonglong2*)p0       = make_ulonglong2(a0[0], a0[1]);
            *(ulonglong2*)(p0 + 4) = make_ulonglong2(a0[2], a0[3]);
            *(ulonglong2*)p1       = make_ulonglong2(a1[0], a1[1]);
            *(ulonglong2*)(p1 + 4) = make_ulonglong2(a1[2], a1[3]);
        }
        __syncthreads();

        // epilogue: thread (u, b) computes cell update
        {
            float gate[4];
#pragma unroll
            for (int g = 0; g < 4; ++g) {
                int cc = g * 8 + u;
                float sum = xgv[g] + biasr[g];
#pragma unroll
                for (int sl = 0; sl < 4; ++sl) sum += part[sl * 1024 + cc * 32 + b];
                gate[g] = sum;
            }
            float iv = 1.0f / (1.0f + __expf(-gate[0]));
            float fv = 1.0f / (1.0f + __expf(-gate[1]));
            float gv = tanhf(gate[2]);
            float ov = 1.0f / (1.0f + __expf(-gate[3]));
            cstate = fv * cstate + iv * gv;
            float hv = ov * tanhf(cstate);
            hnext[(j0 + u) * 32 + b] = hv;
            psum[tid] = hv * wfc;
        }
        __syncthreads();
        if (tid < 32) {
            float tot = 0.0f;
#pragma unroll
            for (int uu = 0; uu < 8; ++uu) tot += psum[tid + uu * 32];
            g_part[blk][t][tid] = tot;
        }
        if (s != T_LEN - 1) bar_sync(dir, 64);
    }
}

// ---------------- kernel 5: reduce partials + sigmoid ----------------
__global__ void finalize_kernel(const float* __restrict__ b_fc, float* __restrict__ out) {
    int g = blockIdx.x * blockDim.x + threadIdx.x;
    if (g >= T_LEN * BATCH) return;
    int t = g >> 5, b = g & 31;
    float acc = b_fc[0];
    const float* p = &g_part[0][t][b];
#pragma unroll 8
    for (int blk = 0; blk < 128; ++blk)
        acc += p[(size_t)blk * T_LEN * BATCH];
    out[(size_t)b * T_LEN + t] = 1.0f / (1.0f + __expf(-acc));
}

// ---------------- launcher ----------------
extern "C" void kernel_launch(void* const* d_in, const int* in_sizes, int n_in,
                              void* d_out, int out_size) {
    const float* x    = (const float*)d_in[0];
    const float* Wx_f = (const float*)d_in[1];
    const float* Wh_f = (const float*)d_in[2];
    const float* b_f  = (const float*)d_in[3];
    const float* Wx_b = (const float*)d_in[4];
    const float* Wh_b = (const float*)d_in[5];
    const float* b_b  = (const float*)d_in[6];
    const float* Wfc  = (const float*)d_in[7];
    const float* bfc  = (const float*)d_in[8];
    float* out = (float*)d_out;
    (void)in_sizes; (void)n_in; (void)out_size;

    cudaFuncSetAttribute(gemm_kernel, cudaFuncAttributeMaxDynamicSharedMemorySize, 65536);
    cudaFuncSetAttribute(lstm_kernel, cudaFuncAttributeMaxDynamicSharedMemorySize, 148480);

    zero_state_kernel<<<256, 256>>>();
    transpose_x_kernel<<<dim3(T_LEN, D_IN / 32), 256>>>(x);
    gemm_kernel<<<dim3(64, 256), 256, 65536>>>(Wx_f, Wx_b);
    lstm_kernel<<<128, 256, 148480>>>(Wh_f, Wh_b, b_f, b_b, Wfc);
    finalize_kernel<<<128, 256>>>(bfc, out);
}